// round 8
// baseline (speedup 1.0000x reference)
#include <cuda_runtime.h>

// Problem constants (fixed by the reference)
#define BB 8
#define TT 2048
#define CC 1024
#define HH 64
#define MM (BB * TT)   // 16384 rows

// Scratch: projected Q, K, V  (4 MB each) — __device__ globals per allocation rules
__device__ float g_Q[MM * HH];
__device__ float g_K[MM * HH];
__device__ float g_V[MM * HH];

// ---------------------------------------------------------------------------
// Projection GEMM: C(16384 x 64) = x(16384 x 1024) @ W(1024 x 64), for 3 Ws.
// 128x64 tile per block, BK=16, 256 threads, 8x4 micro-tile per thread.
// ---------------------------------------------------------------------------
__global__ __launch_bounds__(256) void proj_kernel(
    const float* __restrict__ x,
    const float* __restrict__ Wk,
    const float* __restrict__ Wq,
    const float* __restrict__ Wv)
{
    __shared__ float As[16][132];   // [k][row], 128 rows + pad
    __shared__ float Bs[16][64];    // [k][n]

    const float* W  = (blockIdx.y == 0) ? Wk : ((blockIdx.y == 1) ? Wq : Wv);
    float*       Out = (blockIdx.y == 0) ? g_K : ((blockIdx.y == 1) ? g_Q : g_V);

    const int tid = threadIdx.x;
    const int tx  = tid & 15;       // n:  tx*4
    const int ty  = tid >> 4;       // m:  ty*8 (0..15 -> 128 rows)
    const int row0 = blockIdx.x * 128;

    float acc[8][4] = {};

    for (int k0 = 0; k0 < CC; k0 += 16) {
        #pragma unroll
        for (int it = 0; it < 2; it++) {
            const int r  = (tid >> 2) + it * 64;   // 0..127
            const int kc = (tid & 3) * 4;
            float4 v = *(const float4*)(x + (size_t)(row0 + r) * CC + k0 + kc);
            As[kc + 0][r] = v.x;
            As[kc + 1][r] = v.y;
            As[kc + 2][r] = v.z;
            As[kc + 3][r] = v.w;
        }
        {
            const int kr = tid >> 4;
            const int nc = (tid & 15) * 4;
            *(float4*)&Bs[kr][nc] = *(const float4*)(W + (size_t)(k0 + kr) * HH + nc);
        }
        __syncthreads();

        #pragma unroll
        for (int kk = 0; kk < 16; kk++) {
            float a[8], b[4];
            *(float4*)&a[0] = *(const float4*)&As[kk][ty * 8];
            *(float4*)&a[4] = *(const float4*)&As[kk][ty * 8 + 4];
            *(float4*)b     = *(const float4*)&Bs[kk][tx * 4];
            #pragma unroll
            for (int r = 0; r < 8; r++)
                #pragma unroll
                for (int c = 0; c < 4; c++)
                    acc[r][c] += a[r] * b[c];
        }
        __syncthreads();
    }

    #pragma unroll
    for (int r = 0; r < 8; r++)
        *(float4*)(Out + (size_t)(row0 + ty * 8 + r) * HH + tx * 4) = *(float4*)acc[r];
}

// ---------------------------------------------------------------------------
// Flash attention v4: block = 64 queries x 64-key tiles, 128 threads
// (16x8 thread grid, 8x4 micro-tiles -> 0.66-0.75 B/FLOP smem intensity).
// Base-2 online softmax with scale folded into Q; PV k-unrolled x4.
// ---------------------------------------------------------------------------
#define QT 64
#define KT 64
#define QS_STRIDE 68
#define KS_STRIDE 68
#define PS_STRIDE 68

#define SM_QS 0
#define SM_KS (SM_QS + 64 * QS_STRIDE)
#define SM_VS (SM_KS + 64 * KS_STRIDE)
#define SM_PS (SM_VS + 64 * 64)
#define SM_TOTAL (SM_PS + QT * PS_STRIDE)     // 17152 floats = 68608 bytes

__global__ __launch_bounds__(128) void attn_kernel(float* __restrict__ out)
{
    extern __shared__ float sm[];
    float (*Qs)[QS_STRIDE] = (float (*)[QS_STRIDE])(sm + SM_QS);   // [d][qrow]
    float (*Ks)[KS_STRIDE] = (float (*)[KS_STRIDE])(sm + SM_KS);   // [d][kcol]
    float (*Vs)[64]        = (float (*)[64])(sm + SM_VS);          // [k][d]
    float (*Ps)[PS_STRIDE] = (float (*)[PS_STRIDE])(sm + SM_PS);   // [qrow][k]

    const int tid = threadIdx.x;
    const int tx  = tid & 15;            // key cols / out dims (x4)
    const int ty  = tid >> 4;            // 0..7 -> query rows (x8)

    const int b  = blockIdx.x & 7;
    const int qt = (TT / QT - 1) - (blockIdx.x >> 3);   // heavy tiles first
    const int q0 = qt * QT;

    const float* Qg = g_Q + ((size_t)b * TT + q0) * HH;
    const float* Kg = g_K + (size_t)b * TT * HH;
    const float* Vg = g_V + (size_t)b * TT * HH;

    // fold softmax scale and log2(e) into Q so the inner softmax is pure exp2
    const float qscale = 0.125f * 1.44269504f;

    // Load Q tile transposed ([d][row]) and pre-scaled: 1024 float4, 8/thread
    #pragma unroll
    for (int it = 0; it < 8; it++) {
        const int i  = tid + it * 128;          // 0..1023
        const int r  = i >> 4;                  // 0..63
        const int dc = (i & 15) * 4;
        float4 v = *(const float4*)(Qg + (size_t)r * HH + dc);
        Qs[dc + 0][r] = v.x * qscale;
        Qs[dc + 1][r] = v.y * qscale;
        Qs[dc + 2][r] = v.z * qscale;
        Qs[dc + 3][r] = v.w * qscale;
    }

    float o[8][4] = {};
    float m[8], l[8];
    #pragma unroll
    for (int r = 0; r < 8; r++) { m[r] = -1e30f; l[r] = 0.f; }

    for (int j0 = 0; j0 <= q0; j0 += KT) {
        __syncthreads();   // previous iter's Vs/Ps readers done

        // Stage K (transposed) and V (natural): 1024 float4 each, 8/thread
        #pragma unroll
        for (int it = 0; it < 8; it++) {
            const int i  = tid + it * 128;      // 0..1023
            const int r  = i >> 4;              // 0..63
            const int dc = (i & 15) * 4;
            float4 kv = *(const float4*)(Kg + (size_t)(j0 + r) * HH + dc);
            Ks[dc + 0][r] = kv.x;
            Ks[dc + 1][r] = kv.y;
            Ks[dc + 2][r] = kv.z;
            Ks[dc + 3][r] = kv.w;
            *(float4*)&Vs[r][dc] = *(const float4*)(Vg + (size_t)(j0 + r) * HH + dc);
        }
        __syncthreads();

        // S tile: s[r][c] = qscaled_q_row . k_col   (8x4 micro, 3 LDS / 32 FFMA)
        float s[8][4] = {};
        #pragma unroll
        for (int d = 0; d < 64; d++) {
            float a[8], bv[4];
            *(float4*)&a[0] = *(const float4*)&Qs[d][ty * 8];
            *(float4*)&a[4] = *(const float4*)&Qs[d][ty * 8 + 4];
            *(float4*)bv    = *(const float4*)&Ks[d][tx * 4];
            #pragma unroll
            for (int r = 0; r < 8; r++)
                #pragma unroll
                for (int c = 0; c < 4; c++)
                    s[r][c] += a[r] * bv[c];
        }

        // Causal mask: only the diagonal tile needs it (QT == KT)
        if (j0 == q0) {
            #pragma unroll
            for (int r = 0; r < 8; r++)
                #pragma unroll
                for (int c = 0; c < 4; c++)
                    if (tx * 4 + c > ty * 8 + r) s[r][c] = -1e30f;
        }

        // Online softmax per query row (16 lanes of a half-warp share rows)
        #pragma unroll
        for (int r = 0; r < 8; r++) {
            float mx = fmaxf(fmaxf(s[r][0], s[r][1]), fmaxf(s[r][2], s[r][3]));
            mx = fmaxf(mx, __shfl_xor_sync(0xffffffffu, mx, 1));
            mx = fmaxf(mx, __shfl_xor_sync(0xffffffffu, mx, 2));
            mx = fmaxf(mx, __shfl_xor_sync(0xffffffffu, mx, 4));
            mx = fmaxf(mx, __shfl_xor_sync(0xffffffffu, mx, 8));

            const float mnew  = fmaxf(m[r], mx);
            const float alpha = exp2f(m[r] - mnew);
            m[r] = mnew;

            float psum = 0.f;
            #pragma unroll
            for (int c = 0; c < 4; c++) {
                const float p = exp2f(s[r][c] - mnew);
                s[r][c] = p;
                psum += p;
            }
            psum += __shfl_xor_sync(0xffffffffu, psum, 1);
            psum += __shfl_xor_sync(0xffffffffu, psum, 2);
            psum += __shfl_xor_sync(0xffffffffu, psum, 4);
            psum += __shfl_xor_sync(0xffffffffu, psum, 8);

            l[r] = l[r] * alpha + psum;
            #pragma unroll
            for (int c = 0; c < 4; c++) o[r][c] *= alpha;
        }

        // Stage P ([row][k]) for the PV GEMM
        #pragma unroll
        for (int r = 0; r < 8; r++)
            *(float4*)&Ps[ty * 8 + r][tx * 4] = *(float4*)s[r];
        __syncthreads();

        // O += P . V   (k unrolled x4: 12 LDS.128 / 128 FFMA)
        #pragma unroll
        for (int k = 0; k < KT; k += 4) {
            float a[8][4], bv[4][4];
            #pragma unroll
            for (int r = 0; r < 8; r++)
                *(float4*)a[r] = *(const float4*)&Ps[ty * 8 + r][k];
            #pragma unroll
            for (int kk = 0; kk < 4; kk++)
                *(float4*)bv[kk] = *(const float4*)&Vs[k + kk][tx * 4];
            #pragma unroll
            for (int r = 0; r < 8; r++)
                #pragma unroll
                for (int kk = 0; kk < 4; kk++)
                    #pragma unroll
                    for (int c = 0; c < 4; c++)
                        o[r][c] += a[r][kk] * bv[kk][c];
        }
    }

    // Normalize and write out
    float* Orow = out + ((size_t)b * TT + q0) * HH;
    #pragma unroll
    for (int r = 0; r < 8; r++) {
        const float inv = 1.f / l[r];
        float4 v;
        v.x = o[r][0] * inv;
        v.y = o[r][1] * inv;
        v.z = o[r][2] * inv;
        v.w = o[r][3] * inv;
        *(float4*)(Orow + (size_t)(ty * 8 + r) * HH + tx * 4) = v;
    }
}

// ---------------------------------------------------------------------------
extern "C" void kernel_launch(void* const* d_in, const int* in_sizes, int n_in,
                              void* d_out, int out_size)
{
    const float* x  = (const float*)d_in[0];
    const float* Wk = (const float*)d_in[1];
    const float* Wq = (const float*)d_in[2];
    const float* Wv = (const float*)d_in[3];
    float* out = (float*)d_out;

    const int smem_bytes = SM_TOTAL * (int)sizeof(float);   // 68608
    cudaFuncSetAttribute(attn_kernel, cudaFuncAttributeMaxDynamicSharedMemorySize, smem_bytes);

    dim3 pgrid(MM / 128, 3);
    proj_kernel<<<pgrid, 256>>>(x, Wk, Wq, Wv);

    attn_kernel<<<BB * (TT / QT), 128, smem_bytes>>>(out);
}

// round 10
// speedup vs baseline: 3.0140x; 3.0140x over previous
#include <cuda_runtime.h>
#include <cstdint>

// Problem constants (fixed by the reference)
#define BB 8
#define TT 2048
#define CC 1024
#define HH 64
#define MM (BB * TT)   // 16384 rows

// Scratch: projected Q, K, V (fp32) — __device__ globals per allocation rules
__device__ float g_Q[MM * HH];
__device__ float g_K[MM * HH];
__device__ float g_V[MM * HH];

// ---------------------------------------------------------------------------
// Helpers: tf32 convert, fast exp2, and the m16n8k8 tf32 tensor-core MMA.
// Fragment mapping (gID = lane>>2, tig = lane&3):
//   A (16x8 row-major): a0=(gID,tig) a1=(gID+8,tig) a2=(gID,tig+4) a3=(gID+8,tig+4)
//   B (8x8  col-major): b0=(k=tig,n=gID) b1=(k=tig+4,n=gID)
//   C (16x8):           c0=(gID,2tig) c1=(gID,2tig+1) c2=(gID+8,2tig) c3=(gID+8,2tig+1)
// ---------------------------------------------------------------------------
__device__ __forceinline__ uint32_t f2tf(float f) {
    uint32_t u;
    asm("cvt.rna.tf32.f32 %0, %1;" : "=r"(u) : "f"(f));
    return u;
}
__device__ __forceinline__ float ex2f(float x) {
    float r;
    asm("ex2.approx.ftz.f32 %0, %1;" : "=f"(r) : "f"(x));
    return r;
}
__device__ __forceinline__ void mma8(float c[4],
                                     uint32_t a0, uint32_t a1, uint32_t a2, uint32_t a3,
                                     uint32_t b0, uint32_t b1) {
    asm volatile(
        "mma.sync.aligned.m16n8k8.row.col.f32.tf32.tf32.f32 "
        "{%0,%1,%2,%3}, {%4,%5,%6,%7}, {%8,%9}, {%0,%1,%2,%3};"
        : "+f"(c[0]), "+f"(c[1]), "+f"(c[2]), "+f"(c[3])
        : "r"(a0), "r"(a1), "r"(a2), "r"(a3), "r"(b0), "r"(b1));
}

// ---------------------------------------------------------------------------
// Projection GEMM (tf32 tensor cores): C(16384x64) = x(16384x1024) @ W(1024x64).
// Block: 128 rows, 256 threads (8 warps x m16), BK=32 per chunk.
// As stride 36 (≡4 mod 32 -> A-frag loads conflict-free),
// Bs stride 72 (≡8 mod 32 -> B-frag loads conflict-free).
// ---------------------------------------------------------------------------
__global__ __launch_bounds__(256) void proj_kernel(
    const float* __restrict__ x,
    const float* __restrict__ Wk,
    const float* __restrict__ Wq,
    const float* __restrict__ Wv)
{
    __shared__ uint32_t As[128][36];   // x tile (tf32), [row][k]
    __shared__ uint32_t Bs[32][72];    // W tile (tf32), [k][n]

    const float* W   = (blockIdx.y == 0) ? Wk : ((blockIdx.y == 1) ? Wq : Wv);
    float*       Out = (blockIdx.y == 0) ? g_K : ((blockIdx.y == 1) ? g_Q : g_V);

    const int tid  = threadIdx.x;
    const int warp = tid >> 5;
    const int lane = tid & 31;
    const int gID  = lane >> 2;
    const int tig  = lane & 3;
    const int row0 = blockIdx.x * 128;

    float acc[8][4] = {};

    for (int k0 = 0; k0 < CC; k0 += 32) {
        // Stage x tile: 128 rows x 32 k  (4 float4 per thread)
        #pragma unroll
        for (int it = 0; it < 4; it++) {
            const int slot = tid + it * 256;       // 0..1023
            const int r    = slot >> 3;            // 0..127
            const int c4   = (slot & 7) * 4;       // 0..28
            float4 v = *(const float4*)(x + (size_t)(row0 + r) * CC + k0 + c4);
            uint4 u = make_uint4(f2tf(v.x), f2tf(v.y), f2tf(v.z), f2tf(v.w));
            *(uint4*)&As[r][c4] = u;
        }
        // Stage W tile: 32 k x 64 n  (2 float4 per thread)
        #pragma unroll
        for (int it = 0; it < 2; it++) {
            const int slot = tid + it * 256;       // 0..511
            const int r    = slot >> 4;            // 0..31
            const int c4   = (slot & 15) * 4;      // 0..60
            float4 v = *(const float4*)(W + (size_t)(k0 + r) * HH + c4);
            uint4 u = make_uint4(f2tf(v.x), f2tf(v.y), f2tf(v.z), f2tf(v.w));
            *(uint4*)&Bs[r][c4] = u;
        }
        __syncthreads();

        #pragma unroll
        for (int ks = 0; ks < 4; ks++) {
            const int k = ks * 8;
            const uint32_t a0 = As[16 * warp + gID    ][k + tig    ];
            const uint32_t a1 = As[16 * warp + gID + 8][k + tig    ];
            const uint32_t a2 = As[16 * warp + gID    ][k + tig + 4];
            const uint32_t a3 = As[16 * warp + gID + 8][k + tig + 4];
            #pragma unroll
            for (int nt = 0; nt < 8; nt++) {
                const uint32_t b0 = Bs[k + tig    ][nt * 8 + gID];
                const uint32_t b1 = Bs[k + tig + 4][nt * 8 + gID];
                mma8(acc[nt], a0, a1, a2, a3, b0, b1);
            }
        }
        __syncthreads();
    }

    // Epilogue: C rows 16w+gID(+8), cols 8nt+2tig(+1)
    const int row = row0 + 16 * warp + gID;
    #pragma unroll
    for (int nt = 0; nt < 8; nt++) {
        const int col = nt * 8 + 2 * tig;
        *(float2*)(Out + (size_t)row * HH + col)       = make_float2(acc[nt][0], acc[nt][1]);
        *(float2*)(Out + (size_t)(row + 8) * HH + col) = make_float2(acc[nt][2], acc[nt][3]);
    }
}

// ---------------------------------------------------------------------------
// Flash attention (tf32 tensor cores): block = 64 queries, 128 threads (4 warps,
// warp w owns query rows 16w..16w+15). 64-key tiles.
//   S = Q·K^T  via mma (A=Q row-major, B=K natural [j][d] -> col-major k8n8)
//   online softmax in fragment space (fp32), P -> warp-private smem (tf32)
//   O += P·V   via mma (A=P, B=V natural [j][d], stride 72)
// Strides: Qs/Ks/Ps 68 (gID-row frag loads), Vs 72 (tig-row frag loads).
// ---------------------------------------------------------------------------
#define AS_QS 0
#define AS_KS (AS_QS + 64 * 68)
#define AS_VS (AS_KS + 64 * 68)
#define AS_PS (AS_VS + 64 * 72)
#define AS_TOTAL (AS_PS + 64 * 68)   // 17664 words = 70656 bytes

__global__ __launch_bounds__(128) void attn_kernel(float* __restrict__ out)
{
    extern __shared__ uint32_t smu[];
    uint32_t (*Qs)[68] = (uint32_t (*)[68])(smu + AS_QS);   // [q][d] tf32 (pre-scaled)
    uint32_t (*Ks)[68] = (uint32_t (*)[68])(smu + AS_KS);   // [j][d] tf32
    uint32_t (*Vs)[72] = (uint32_t (*)[72])(smu + AS_VS);   // [j][d] tf32
    uint32_t (*Ps)[68] = (uint32_t (*)[68])(smu + AS_PS);   // [q][j] tf32 (warp-private rows)

    const int tid  = threadIdx.x;
    const int warp = tid >> 5;
    const int lane = tid & 31;
    const int gID  = lane >> 2;
    const int tig  = lane & 3;

    const int b  = blockIdx.x & 7;
    const int qt = 31 - (blockIdx.x >> 3);   // heavy tiles first
    const int q0 = qt * 64;

    const float* Qg = g_Q + ((size_t)b * TT + q0) * HH;
    const float* Kg = g_K + (size_t)b * TT * HH;
    const float* Vg = g_V + (size_t)b * TT * HH;

    const float qscale = 0.125f * 1.44269504f;   // 1/sqrt(64) * log2(e)

    // Stage Q (scaled + tf32): 64x64, 8 float4 per thread
    #pragma unroll
    for (int it = 0; it < 8; it++) {
        const int slot = tid + it * 128;     // 0..1023
        const int r    = slot >> 4;          // 0..63
        const int c4   = (slot & 15) * 4;
        float4 v = *(const float4*)(Qg + (size_t)r * HH + c4);
        uint4 u = make_uint4(f2tf(v.x * qscale), f2tf(v.y * qscale),
                             f2tf(v.z * qscale), f2tf(v.w * qscale));
        *(uint4*)&Qs[r][c4] = u;
    }

    float o[8][4] = {};
    float m0 = -1e30f, m1 = -1e30f, l0 = 0.f, l1 = 0.f;

    for (int j0 = 0; j0 <= q0; j0 += 64) {
        __syncthreads();   // prev iteration's Ks/Vs readers done (also covers Q staging)

        // Stage K and V tiles (tf32)
        #pragma unroll
        for (int it = 0; it < 8; it++) {
            const int slot = tid + it * 128;
            const int r    = slot >> 4;
            const int c4   = (slot & 15) * 4;
            float4 kv = *(const float4*)(Kg + (size_t)(j0 + r) * HH + c4);
            *(uint4*)&Ks[r][c4] = make_uint4(f2tf(kv.x), f2tf(kv.y), f2tf(kv.z), f2tf(kv.w));
            float4 vv = *(const float4*)(Vg + (size_t)(j0 + r) * HH + c4);
            *(uint4*)&Vs[r][c4] = make_uint4(f2tf(vv.x), f2tf(vv.y), f2tf(vv.z), f2tf(vv.w));
        }
        __syncthreads();

        // ---- S = Q . K^T  (warp: 16 q-rows x 64 j-cols = 8 n-tiles) ----
        float s[8][4] = {};
        #pragma unroll
        for (int ks = 0; ks < 8; ks++) {
            const int k = ks * 8;
            const uint32_t a0 = Qs[16 * warp + gID    ][k + tig    ];
            const uint32_t a1 = Qs[16 * warp + gID + 8][k + tig    ];
            const uint32_t a2 = Qs[16 * warp + gID    ][k + tig + 4];
            const uint32_t a3 = Qs[16 * warp + gID + 8][k + tig + 4];
            #pragma unroll
            for (int nt = 0; nt < 8; nt++) {
                const uint32_t b0 = Ks[nt * 8 + gID][k + tig    ];
                const uint32_t b1 = Ks[nt * 8 + gID][k + tig + 4];
                mma8(s[nt], a0, a1, a2, a3, b0, b1);
            }
        }

        // Causal mask: only diagonal tile
        if (j0 == q0) {
            const int ql0 = 16 * warp + gID;
            const int ql1 = ql0 + 8;
            #pragma unroll
            for (int nt = 0; nt < 8; nt++) {
                const int jc = nt * 8 + 2 * tig;
                if (jc     > ql0) s[nt][0] = -1e30f;
                if (jc + 1 > ql0) s[nt][1] = -1e30f;
                if (jc     > ql1) s[nt][2] = -1e30f;
                if (jc + 1 > ql1) s[nt][3] = -1e30f;
            }
        }

        // ---- online softmax (rows gID and gID+8; 4-lane groups share a row) ----
        float mx0 = -1e30f, mx1 = -1e30f;
        #pragma unroll
        for (int nt = 0; nt < 8; nt++) {
            mx0 = fmaxf(mx0, fmaxf(s[nt][0], s[nt][1]));
            mx1 = fmaxf(mx1, fmaxf(s[nt][2], s[nt][3]));
        }
        mx0 = fmaxf(mx0, __shfl_xor_sync(0xffffffffu, mx0, 1));
        mx0 = fmaxf(mx0, __shfl_xor_sync(0xffffffffu, mx0, 2));
        mx1 = fmaxf(mx1, __shfl_xor_sync(0xffffffffu, mx1, 1));
        mx1 = fmaxf(mx1, __shfl_xor_sync(0xffffffffu, mx1, 2));

        const float mn0 = fmaxf(m0, mx0);
        const float mn1 = fmaxf(m1, mx1);
        const float al0 = ex2f(m0 - mn0);
        const float al1 = ex2f(m1 - mn1);
        m0 = mn0; m1 = mn1;

        float ps0 = 0.f, ps1 = 0.f;
        #pragma unroll
        for (int nt = 0; nt < 8; nt++) {
            s[nt][0] = ex2f(s[nt][0] - mn0);  ps0 += s[nt][0];
            s[nt][1] = ex2f(s[nt][1] - mn0);  ps0 += s[nt][1];
            s[nt][2] = ex2f(s[nt][2] - mn1);  ps1 += s[nt][2];
            s[nt][3] = ex2f(s[nt][3] - mn1);  ps1 += s[nt][3];
        }
        ps0 += __shfl_xor_sync(0xffffffffu, ps0, 1);
        ps0 += __shfl_xor_sync(0xffffffffu, ps0, 2);
        ps1 += __shfl_xor_sync(0xffffffffu, ps1, 1);
        ps1 += __shfl_xor_sync(0xffffffffu, ps1, 2);

        l0 = l0 * al0 + ps0;
        l1 = l1 * al1 + ps1;
        #pragma unroll
        for (int nt = 0; nt < 8; nt++) {
            o[nt][0] *= al0;  o[nt][1] *= al0;
            o[nt][2] *= al1;  o[nt][3] *= al1;
        }

        // ---- P -> smem (warp-private rows), then O += P . V ----
        {
            const int r0 = 16 * warp + gID;
            #pragma unroll
            for (int nt = 0; nt < 8; nt++) {
                const int col = nt * 8 + 2 * tig;
                *(uint2*)&Ps[r0][col]     = make_uint2(f2tf(s[nt][0]), f2tf(s[nt][1]));
                *(uint2*)&Ps[r0 + 8][col] = make_uint2(f2tf(s[nt][2]), f2tf(s[nt][3]));
            }
        }
        __syncwarp();

        #pragma unroll
        for (int ks = 0; ks < 8; ks++) {
            const int k = ks * 8;   // j-chunk
            const uint32_t a0 = Ps[16 * warp + gID    ][k + tig    ];
            const uint32_t a1 = Ps[16 * warp + gID + 8][k + tig    ];
            const uint32_t a2 = Ps[16 * warp + gID    ][k + tig + 4];
            const uint32_t a3 = Ps[16 * warp + gID + 8][k + tig + 4];
            #pragma unroll
            for (int nt = 0; nt < 8; nt++) {
                const uint32_t b0 = Vs[k + tig    ][nt * 8 + gID];
                const uint32_t b1 = Vs[k + tig + 4][nt * 8 + gID];
                mma8(o[nt], a0, a1, a2, a3, b0, b1);
            }
        }
    }

    // Normalize and write out
    const float inv0 = 1.f / l0;
    const float inv1 = 1.f / l1;
    const int row = q0 + 16 * warp + gID;
    float* Ob = out + (size_t)b * TT * HH;
    #pragma unroll
    for (int nt = 0; nt < 8; nt++) {
        const int col = nt * 8 + 2 * tig;
        *(float2*)(Ob + (size_t)row * HH + col) =
            make_float2(o[nt][0] * inv0, o[nt][1] * inv0);
        *(float2*)(Ob + (size_t)(row + 8) * HH + col) =
            make_float2(o[nt][2] * inv1, o[nt][3] * inv1);
    }
}

// ---------------------------------------------------------------------------
extern "C" void kernel_launch(void* const* d_in, const int* in_sizes, int n_in,
                              void* d_out, int out_size)
{
    const float* x  = (const float*)d_in[0];
    const float* Wk = (const float*)d_in[1];
    const float* Wq = (const float*)d_in[2];
    const float* Wv = (const float*)d_in[3];
    float* out = (float*)d_out;

    const int smem_bytes = AS_TOTAL * (int)sizeof(uint32_t);   // 70656
    cudaFuncSetAttribute(attn_kernel, cudaFuncAttributeMaxDynamicSharedMemorySize, smem_bytes);

    dim3 pgrid(MM / 128, 3);
    proj_kernel<<<pgrid, 256>>>(x, Wk, Wq, Wv);

    attn_kernel<<<BB * (TT / 64), 128, smem_bytes>>>(out);
}

// round 14
// speedup vs baseline: 3.0624x; 1.0161x over previous
#include <cuda_runtime.h>
#include <cstdint>

// Problem constants (fixed by the reference)
#define BB 8
#define TT 2048
#define CC 1024
#define HH 64
#define MM (BB * TT)   // 16384 rows

// Scratch: projected Q, K, V stored as TF32 bit patterns (Q pre-scaled).
__device__ uint32_t g_Q[MM * HH];
__device__ uint32_t g_K[MM * HH];
__device__ uint32_t g_V[MM * HH];

// ---------------------------------------------------------------------------
// Helpers: tf32 convert, fast exp2, m16n8k8 tf32 MMA.
// Fragment mapping (gID = lane>>2, tig = lane&3):
//   A (16x8 row-major): a0=(gID,tig) a1=(gID+8,tig) a2=(gID,tig+4) a3=(gID+8,tig+4)
//   B (8x8  col-major): b0=(k=tig,n=gID) b1=(k=tig+4,n=gID)
//   C (16x8):           c0=(gID,2tig) c1=(gID,2tig+1) c2=(gID+8,2tig) c3=(gID+8,2tig+1)
// ---------------------------------------------------------------------------
__device__ __forceinline__ uint32_t f2tf(float f) {
    uint32_t u;
    asm("cvt.rna.tf32.f32 %0, %1;" : "=r"(u) : "f"(f));
    return u;
}
__device__ __forceinline__ float ex2f(float x) {
    float r;
    asm("ex2.approx.ftz.f32 %0, %1;" : "=f"(r) : "f"(x));
    return r;
}
__device__ __forceinline__ void mma8(float c[4],
                                     uint32_t a0, uint32_t a1, uint32_t a2, uint32_t a3,
                                     uint32_t b0, uint32_t b1) {
    asm volatile(
        "mma.sync.aligned.m16n8k8.row.col.f32.tf32.tf32.f32 "
        "{%0,%1,%2,%3}, {%4,%5,%6,%7}, {%8,%9}, {%0,%1,%2,%3};"
        : "+f"(c[0]), "+f"(c[1]), "+f"(c[2]), "+f"(c[3])
        : "r"(a0), "r"(a1), "r"(a2), "r"(a3), "r"(b0), "r"(b1));
}
#define BARG(id) asm volatile("bar.sync %0, %1;" :: "r"(id), "r"(64) : "memory")

// ---------------------------------------------------------------------------
// Fused projection GEMM (tf32): {K,Q,V}(16384x64) = x(16384x1024) @ W*(1024x64).
// Block: 64 x-rows, 128 threads (4 warps x m16), BK=32; x staged ONCE for all
// three outputs. Outputs stored as tf32 (Q pre-scaled by 1/8*log2(e)).
// As stride 36 (banks 4g+t), Bs stride 72 (banks 8t+g) -> conflict-free frags.
// ---------------------------------------------------------------------------
__global__ __launch_bounds__(128) void proj_kernel(
    const float* __restrict__ x,
    const float* __restrict__ Wk,
    const float* __restrict__ Wq,
    const float* __restrict__ Wv)
{
    __shared__ uint32_t As[64][36];       // x tile (tf32), [row][k]
    __shared__ uint32_t Bs[3][32][72];    // W tiles (tf32), [w][k][n]

    const int tid  = threadIdx.x;
    const int warp = tid >> 5;
    const int lane = tid & 31;
    const int gID  = lane >> 2;
    const int tig  = lane & 3;
    const int row0 = blockIdx.x * 64;

    float aK[8][4] = {}, aQ[8][4] = {}, aV[8][4] = {};

    for (int k0 = 0; k0 < CC; k0 += 32) {
        // Stage x tile: 64 rows x 32 k = 512 uint4, 4 per thread
        #pragma unroll
        for (int it = 0; it < 4; it++) {
            const int s  = tid + it * 128;
            const int r  = s >> 3;
            const int c4 = (s & 7) * 4;
            float4 v = *(const float4*)(x + (size_t)(row0 + r) * CC + k0 + c4);
            *(uint4*)&As[r][c4] = make_uint4(f2tf(v.x), f2tf(v.y), f2tf(v.z), f2tf(v.w));
        }
        // Stage all three W tiles: 3 x 32 x 64 = 1536 uint4, 12 per thread
        #pragma unroll
        for (int it = 0; it < 12; it++) {
            const int s    = tid + it * 128;
            const int wsel = s >> 9;
            const int rem  = s & 511;
            const int r    = rem >> 4;
            const int c4   = (rem & 15) * 4;
            const float* Wp = (wsel == 0) ? Wk : ((wsel == 1) ? Wq : Wv);
            float4 v = *(const float4*)(Wp + (size_t)(k0 + r) * HH + c4);
            *(uint4*)&Bs[wsel][r][c4] = make_uint4(f2tf(v.x), f2tf(v.y), f2tf(v.z), f2tf(v.w));
        }
        __syncthreads();

        #pragma unroll
        for (int ks = 0; ks < 4; ks++) {
            const int k = ks * 8;
            const uint32_t a0 = As[16 * warp + gID    ][k + tig    ];
            const uint32_t a1 = As[16 * warp + gID + 8][k + tig    ];
            const uint32_t a2 = As[16 * warp + gID    ][k + tig + 4];
            const uint32_t a3 = As[16 * warp + gID + 8][k + tig + 4];
            #pragma unroll
            for (int nt = 0; nt < 8; nt++) {
                mma8(aK[nt], a0, a1, a2, a3, Bs[0][k + tig][nt * 8 + gID], Bs[0][k + tig + 4][nt * 8 + gID]);
                mma8(aQ[nt], a0, a1, a2, a3, Bs[1][k + tig][nt * 8 + gID], Bs[1][k + tig + 4][nt * 8 + gID]);
                mma8(aV[nt], a0, a1, a2, a3, Bs[2][k + tig][nt * 8 + gID], Bs[2][k + tig + 4][nt * 8 + gID]);
            }
        }
        __syncthreads();
    }

    // Epilogue: tf32 stores; Q pre-scaled by 1/sqrt(64)*log2(e)
    const float qscale = 0.125f * 1.44269504f;
    const size_t row = row0 + 16 * warp + gID;
    #pragma unroll
    for (int nt = 0; nt < 8; nt++) {
        const int col = nt * 8 + 2 * tig;
        *(uint2*)(g_K + row * HH + col)       = make_uint2(f2tf(aK[nt][0]), f2tf(aK[nt][1]));
        *(uint2*)(g_K + (row + 8) * HH + col) = make_uint2(f2tf(aK[nt][2]), f2tf(aK[nt][3]));
        *(uint2*)(g_Q + row * HH + col)       = make_uint2(f2tf(aQ[nt][0] * qscale), f2tf(aQ[nt][1] * qscale));
        *(uint2*)(g_Q + (row + 8) * HH + col) = make_uint2(f2tf(aQ[nt][2] * qscale), f2tf(aQ[nt][3] * qscale));
        *(uint2*)(g_V + row * HH + col)       = make_uint2(f2tf(aV[nt][0]), f2tf(aV[nt][1]));
        *(uint2*)(g_V + (row + 8) * HH + col) = make_uint2(f2tf(aV[nt][2]), f2tf(aV[nt][3]));
    }
}

// ---------------------------------------------------------------------------
// Flash attention (tf32, split-j): block = 32 queries, 128 threads = 2 groups
// of 2 warps. Group g processes 32-key tiles with (j0/32)%2 == g using its own
// K/V/P smem + named barrier; partial (o,m,l) merged at the end via smem.
// All staging is pure uint4 copies (inputs pre-converted to tf32).
// ---------------------------------------------------------------------------
#define AT_QS 0                                  // Qs: 32*68 = 2176 words
#define G_WORDS (32*68 + 32*72 + 32*36)          // Ks+Vs+Ps = 5632 words/group
#define AT_G  (AT_QS + 32*68)
#define AT_CO (AT_G + 2*G_WORDS)                 // combine o: 2048 floats
#define AT_CML (AT_CO + 2048)                    // combine m/l: 256 floats
#define AT_TOTAL (AT_CML + 256)                  // 15744 words = 62976 B

__global__ __launch_bounds__(128) void attn_kernel(float* __restrict__ out)
{
    extern __shared__ uint32_t smu[];
    const int tid  = threadIdx.x;
    const int warp = tid >> 5;
    const int lane = tid & 31;
    const int gID  = lane >> 2;
    const int tig  = lane & 3;
    const int grp  = warp >> 1;          // 0 / 1
    const int wg   = warp & 1;           // 16-row half within the 32-q tile
    const int lt   = tid & 63;           // group-local thread id

    uint32_t (*Qs)[68] = (uint32_t (*)[68])(smu + AT_QS);
    uint32_t* gbase = smu + AT_G + grp * G_WORDS;
    uint32_t (*Ks)[68] = (uint32_t (*)[68])(gbase);
    uint32_t (*Vs)[72] = (uint32_t (*)[72])(gbase + 32 * 68);
    uint32_t (*Ps)[36] = (uint32_t (*)[36])(gbase + 32 * 68 + 32 * 72);
    float* Co  = (float*)(smu + AT_CO);
    float* Cml = (float*)(smu + AT_CML);

    const int b  = blockIdx.x & 7;
    const int qt = 63 - (blockIdx.x >> 3);     // heavy tiles first
    const int q0 = qt * 32;

    const uint32_t* Qg = g_Q + ((size_t)b * TT + q0) * HH;
    const uint32_t* Kg = g_K + (size_t)b * TT * HH;
    const uint32_t* Vg = g_V + (size_t)b * TT * HH;

    // Stage Q (already tf32 + scaled): 32x64 = 512 uint4, 4 per thread
    #pragma unroll
    for (int it = 0; it < 4; it++) {
        const int s  = tid + it * 128;
        const int r  = s >> 4;
        const int c4 = (s & 15) * 4;
        *(uint4*)&Qs[r][c4] = *(const uint4*)(Qg + (size_t)r * HH + c4);
    }
    __syncthreads();

    float o[8][4] = {};
    float m0 = -1e30f, m1 = -1e30f, l0 = 0.f, l1 = 0.f;

    for (int j0 = grp * 32; j0 <= q0; j0 += 64) {
        BARG(grp + 1);   // group's previous compute done

        // Stage K and V 32x64 tiles: 512 uint4 each, 8 per group-thread
        #pragma unroll
        for (int it = 0; it < 8; it++) {
            const int s  = lt + it * 64;
            const int r  = s >> 4;
            const int c4 = (s & 15) * 4;
            *(uint4*)&Ks[r][c4] = *(const uint4*)(Kg + (size_t)(j0 + r) * HH + c4);
            *(uint4*)&Vs[r][c4] = *(const uint4*)(Vg + (size_t)(j0 + r) * HH + c4);
        }
        BARG(grp + 1);

        // ---- S = Q.K^T : warp rows 16wg+gID/+8, 32 key cols (4 n-tiles) ----
        float s[4][4] = {};
        #pragma unroll
        for (int ks = 0; ks < 8; ks++) {
            const int k = ks * 8;
            const uint32_t a0 = Qs[16 * wg + gID    ][k + tig    ];
            const uint32_t a1 = Qs[16 * wg + gID + 8][k + tig    ];
            const uint32_t a2 = Qs[16 * wg + gID    ][k + tig + 4];
            const uint32_t a3 = Qs[16 * wg + gID + 8][k + tig + 4];
            #pragma unroll
            for (int nt = 0; nt < 4; nt++) {
                mma8(s[nt], a0, a1, a2, a3,
                     Ks[nt * 8 + gID][k + tig], Ks[nt * 8 + gID][k + tig + 4]);
            }
        }

        // Causal mask: only the diagonal tile
        if (j0 == q0) {
            const int ql0 = 16 * wg + gID;
            const int ql1 = ql0 + 8;
            #pragma unroll
            for (int nt = 0; nt < 4; nt++) {
                const int jc = nt * 8 + 2 * tig;
                if (jc     > ql0) s[nt][0] = -1e30f;
                if (jc + 1 > ql0) s[nt][1] = -1e30f;
                if (jc     > ql1) s[nt][2] = -1e30f;
                if (jc + 1 > ql1) s[nt][3] = -1e30f;
            }
        }

        // ---- online softmax (rows gID / gID+8; 4-lane groups share rows) ----
        float mx0 = -1e30f, mx1 = -1e30f;
        #pragma unroll
        for (int nt = 0; nt < 4; nt++) {
            mx0 = fmaxf(mx0, fmaxf(s[nt][0], s[nt][1]));
            mx1 = fmaxf(mx1, fmaxf(s[nt][2], s[nt][3]));
        }
        mx0 = fmaxf(mx0, __shfl_xor_sync(0xffffffffu, mx0, 1));
        mx0 = fmaxf(mx0, __shfl_xor_sync(0xffffffffu, mx0, 2));
        mx1 = fmaxf(mx1, __shfl_xor_sync(0xffffffffu, mx1, 1));
        mx1 = fmaxf(mx1, __shfl_xor_sync(0xffffffffu, mx1, 2));

        const float mn0 = fmaxf(m0, mx0);
        const float mn1 = fmaxf(m1, mx1);
        const float al0 = ex2f(m0 - mn0);
        const float al1 = ex2f(m1 - mn1);
        m0 = mn0; m1 = mn1;

        float ps0 = 0.f, ps1 = 0.f;
        #pragma unroll
        for (int nt = 0; nt < 4; nt++) {
            s[nt][0] = ex2f(s[nt][0] - mn0);  ps0 += s[nt][0];
            s[nt][1] = ex2f(s[nt][1] - mn0);  ps0 += s[nt][1];
            s[nt][2] = ex2f(s[nt][2] - mn1);  ps1 += s[nt][2];
            s[nt][3] = ex2f(s[nt][3] - mn1);  ps1 += s[nt][3];
        }
        ps0 += __shfl_xor_sync(0xffffffffu, ps0, 1);
        ps0 += __shfl_xor_sync(0xffffffffu, ps0, 2);
        ps1 += __shfl_xor_sync(0xffffffffu, ps1, 1);
        ps1 += __shfl_xor_sync(0xffffffffu, ps1, 2);

        l0 = l0 * al0 + ps0;
        l1 = l1 * al1 + ps1;
        #pragma unroll
        for (int nt = 0; nt < 8; nt++) {
            o[nt][0] *= al0;  o[nt][1] *= al0;
            o[nt][2] *= al1;  o[nt][3] *= al1;
        }

        // ---- P -> warp-private smem rows, then O += P.V ----
        {
            const int r0 = 16 * wg + gID;
            #pragma unroll
            for (int nt = 0; nt < 4; nt++) {
                const int col = nt * 8 + 2 * tig;
                *(uint2*)&Ps[r0][col]     = make_uint2(f2tf(s[nt][0]), f2tf(s[nt][1]));
                *(uint2*)&Ps[r0 + 8][col] = make_uint2(f2tf(s[nt][2]), f2tf(s[nt][3]));
            }
        }
        __syncwarp();

        #pragma unroll
        for (int ks = 0; ks < 4; ks++) {
            const int k = ks * 8;
            const uint32_t a0 = Ps[16 * wg + gID    ][k + tig    ];
            const uint32_t a1 = Ps[16 * wg + gID + 8][k + tig    ];
            const uint32_t a2 = Ps[16 * wg + gID    ][k + tig + 4];
            const uint32_t a3 = Ps[16 * wg + gID + 8][k + tig + 4];
            #pragma unroll
            for (int nt = 0; nt < 8; nt++) {
                mma8(o[nt], a0, a1, a2, a3,
                     Vs[k + tig][nt * 8 + gID], Vs[k + tig + 4][nt * 8 + gID]);
            }
        }
    }

    // ---- merge the two groups' partials ----
    if (grp == 1) {
        #pragma unroll
        for (int nt = 0; nt < 8; nt++)
            #pragma unroll
            for (int c = 0; c < 4; c++)
                Co[((wg * 8 + nt) * 4 + c) * 32 + lane] = o[nt][c];
        Cml[(wg * 4 + 0) * 32 + lane] = m0;
        Cml[(wg * 4 + 1) * 32 + lane] = m1;
        Cml[(wg * 4 + 2) * 32 + lane] = l0;
        Cml[(wg * 4 + 3) * 32 + lane] = l1;
    }
    __syncthreads();

    if (grp == 0) {
        const float m0p = Cml[(wg * 4 + 0) * 32 + lane];
        const float m1p = Cml[(wg * 4 + 1) * 32 + lane];
        const float l0p = Cml[(wg * 4 + 2) * 32 + lane];
        const float l1p = Cml[(wg * 4 + 3) * 32 + lane];

        const float M0 = fmaxf(m0, m0p), M1 = fmaxf(m1, m1p);
        const float s00 = ex2f(m0 - M0), s01 = ex2f(m0p - M0);
        const float s10 = ex2f(m1 - M1), s11 = ex2f(m1p - M1);
        const float i0 = 1.f / (l0 * s00 + l0p * s01);
        const float i1 = 1.f / (l1 * s10 + l1p * s11);

        const int row = q0 + 16 * wg + gID;
        float* Ob = out + (size_t)b * TT * HH;
        #pragma unroll
        for (int nt = 0; nt < 8; nt++) {
            const int col = nt * 8 + 2 * tig;
            const float p0 = Co[((wg * 8 + nt) * 4 + 0) * 32 + lane];
            const float p1 = Co[((wg * 8 + nt) * 4 + 1) * 32 + lane];
            const float p2 = Co[((wg * 8 + nt) * 4 + 2) * 32 + lane];
            const float p3 = Co[((wg * 8 + nt) * 4 + 3) * 32 + lane];
            *(float2*)(Ob + (size_t)row * HH + col) =
                make_float2((o[nt][0] * s00 + p0 * s01) * i0,
                            (o[nt][1] * s00 + p1 * s01) * i0);
            *(float2*)(Ob + (size_t)(row + 8) * HH + col) =
                make_float2((o[nt][2] * s10 + p2 * s11) * i1,
                            (o[nt][3] * s10 + p3 * s11) * i1);
        }
    }
}

// ---------------------------------------------------------------------------
extern "C" void kernel_launch(void* const* d_in, const int* in_sizes, int n_in,
                              void* d_out, int out_size)
{
    const float* x  = (const float*)d_in[0];
    const float* Wk = (const float*)d_in[1];
    const float* Wq = (const float*)d_in[2];
    const float* Wv = (const float*)d_in[3];
    float* out = (float*)d_out;

    const int smem_bytes = AT_TOTAL * (int)sizeof(uint32_t);   // 62976
    cudaFuncSetAttribute(attn_kernel, cudaFuncAttributeMaxDynamicSharedMemorySize, smem_bytes);

    proj_kernel<<<MM / 64, 128>>>(x, Wk, Wq, Wv);

    attn_kernel<<<BB * (TT / 32), 128, smem_bytes>>>(out);
}

// round 15
// speedup vs baseline: 3.5844x; 1.1705x over previous
#include <cuda_runtime.h>
#include <cstdint>

// Problem constants (fixed by the reference)
#define BB 8
#define TT 2048
#define CC 1024
#define HH 64
#define MM (BB * TT)   // 16384 rows

// Scratch (tf32 bit patterns): Q pre-scaled; V stored TRANSPOSED [b][d][t].
__device__ uint32_t g_Q[MM * HH];
__device__ uint32_t g_K[MM * HH];
__device__ uint32_t g_V[MM * HH];

// ---------------------------------------------------------------------------
// Helpers
// ---------------------------------------------------------------------------
__device__ __forceinline__ uint32_t f2tf(float f) {
    uint32_t u;
    asm("cvt.rna.tf32.f32 %0, %1;" : "=r"(u) : "f"(f));
    return u;
}
__device__ __forceinline__ float ex2f(float x) {
    float r;
    asm("ex2.approx.ftz.f32 %0, %1;" : "=f"(r) : "f"(x));
    return r;
}
__device__ __forceinline__ void mma8(float c[4],
                                     uint32_t a0, uint32_t a1, uint32_t a2, uint32_t a3,
                                     uint32_t b0, uint32_t b1) {
    asm volatile(
        "mma.sync.aligned.m16n8k8.row.col.f32.tf32.tf32.f32 "
        "{%0,%1,%2,%3}, {%4,%5,%6,%7}, {%8,%9}, {%0,%1,%2,%3};"
        : "+f"(c[0]), "+f"(c[1]), "+f"(c[2]), "+f"(c[3])
        : "r"(a0), "r"(a1), "r"(a2), "r"(a3), "r"(b0), "r"(b1));
}
__device__ __forceinline__ void ldsm4(uint32_t& r0, uint32_t& r1, uint32_t& r2, uint32_t& r3,
                                      uint32_t addr) {
    asm volatile("ldmatrix.sync.aligned.x4.m8n8.shared.b16 {%0,%1,%2,%3}, [%4];"
                 : "=r"(r0), "=r"(r1), "=r"(r2), "=r"(r3) : "r"(addr));
}
__device__ __forceinline__ uint32_t smem_u32(const void* p) {
    uint32_t a;
    asm("{ .reg .u64 t; cvta.to.shared.u64 t, %1; cvt.u32.u64 %0, t; }" : "=r"(a) : "l"(p));
    return a;
}
#define CP_ASYNC16(dst, src) \
    asm volatile("cp.async.ca.shared.global [%0], [%1], 16;" :: "r"(dst), "l"(src))
#define CP_COMMIT  asm volatile("cp.async.commit_group;" ::: "memory")
#define CP_WAIT0   asm volatile("cp.async.wait_group 0;" ::: "memory")
#define CP_WAIT1   asm volatile("cp.async.wait_group 1;" ::: "memory")
#define BARG(id)   asm volatile("bar.sync %0, %1;" :: "r"(id), "r"(64) : "memory")

// ---------------------------------------------------------------------------
// Fused projection GEMM (tf32): {K,Q,V} = x @ W*.  64 rows/block, 4 warps.
// Unchanged except V epilogue now writes the TRANSPOSED layout g_V[b][d][t].
// ---------------------------------------------------------------------------
__global__ __launch_bounds__(128) void proj_kernel(
    const float* __restrict__ x,
    const float* __restrict__ Wk,
    const float* __restrict__ Wq,
    const float* __restrict__ Wv)
{
    __shared__ uint32_t As[64][36];
    __shared__ uint32_t Bs[3][32][72];

    const int tid  = threadIdx.x;
    const int warp = tid >> 5;
    const int lane = tid & 31;
    const int gID  = lane >> 2;
    const int tig  = lane & 3;
    const int row0 = blockIdx.x * 64;

    float aK[8][4] = {}, aQ[8][4] = {}, aV[8][4] = {};

    for (int k0 = 0; k0 < CC; k0 += 32) {
        #pragma unroll
        for (int it = 0; it < 4; it++) {
            const int s  = tid + it * 128;
            const int r  = s >> 3;
            const int c4 = (s & 7) * 4;
            float4 v = *(const float4*)(x + (size_t)(row0 + r) * CC + k0 + c4);
            *(uint4*)&As[r][c4] = make_uint4(f2tf(v.x), f2tf(v.y), f2tf(v.z), f2tf(v.w));
        }
        #pragma unroll
        for (int it = 0; it < 12; it++) {
            const int s    = tid + it * 128;
            const int wsel = s >> 9;
            const int rem  = s & 511;
            const int r    = rem >> 4;
            const int c4   = (rem & 15) * 4;
            const float* Wp = (wsel == 0) ? Wk : ((wsel == 1) ? Wq : Wv);
            float4 v = *(const float4*)(Wp + (size_t)(k0 + r) * HH + c4);
            *(uint4*)&Bs[wsel][r][c4] = make_uint4(f2tf(v.x), f2tf(v.y), f2tf(v.z), f2tf(v.w));
        }
        __syncthreads();

        #pragma unroll
        for (int ks = 0; ks < 4; ks++) {
            const int k = ks * 8;
            const uint32_t a0 = As[16 * warp + gID    ][k + tig    ];
            const uint32_t a1 = As[16 * warp + gID + 8][k + tig    ];
            const uint32_t a2 = As[16 * warp + gID    ][k + tig + 4];
            const uint32_t a3 = As[16 * warp + gID + 8][k + tig + 4];
            #pragma unroll
            for (int nt = 0; nt < 8; nt++) {
                mma8(aK[nt], a0, a1, a2, a3, Bs[0][k + tig][nt * 8 + gID], Bs[0][k + tig + 4][nt * 8 + gID]);
                mma8(aQ[nt], a0, a1, a2, a3, Bs[1][k + tig][nt * 8 + gID], Bs[1][k + tig + 4][nt * 8 + gID]);
                mma8(aV[nt], a0, a1, a2, a3, Bs[2][k + tig][nt * 8 + gID], Bs[2][k + tig + 4][nt * 8 + gID]);
            }
        }
        __syncthreads();
    }

    const float qscale = 0.125f * 1.44269504f;
    const size_t row = row0 + 16 * warp + gID;
    const int bb   = row0 >> 11;          // batch
    const int trow = (row0 & 2047) + 16 * warp + gID;
    uint32_t* Vt = g_V + (size_t)bb * HH * TT;

    #pragma unroll
    for (int nt = 0; nt < 8; nt++) {
        const int col = nt * 8 + 2 * tig;
        *(uint2*)(g_K + row * HH + col)       = make_uint2(f2tf(aK[nt][0]), f2tf(aK[nt][1]));
        *(uint2*)(g_K + (row + 8) * HH + col) = make_uint2(f2tf(aK[nt][2]), f2tf(aK[nt][3]));
        *(uint2*)(g_Q + row * HH + col)       = make_uint2(f2tf(aQ[nt][0] * qscale), f2tf(aQ[nt][1] * qscale));
        *(uint2*)(g_Q + (row + 8) * HH + col) = make_uint2(f2tf(aQ[nt][2] * qscale), f2tf(aQ[nt][3] * qscale));
        // V transposed: element (trow, col) -> Vt[col * TT + trow]
        Vt[(size_t)(col + 0) * TT + trow]     = f2tf(aV[nt][0]);
        Vt[(size_t)(col + 1) * TT + trow]     = f2tf(aV[nt][1]);
        Vt[(size_t)(col + 0) * TT + trow + 8] = f2tf(aV[nt][2]);
        Vt[(size_t)(col + 1) * TT + trow + 8] = f2tf(aV[nt][3]);
    }
}

// ---------------------------------------------------------------------------
// Flash attention v6: 32 queries/block, 2 j-groups of 2 warps; cp.async
// double-buffered K/Vt staging; all fragments via ldmatrix.x4.
//   Qs[32][68], per group: Ks[2][32][68], Vt[2][64][36], Ps[32][36].
// Combine area overlays the (dead-at-merge-time) Ps regions.
// ---------------------------------------------------------------------------
#define AT_QS 0
#define AT_KS (AT_QS + 32 * 68)            // 2176
#define KS_G  (2 * 32 * 68)                // 4352 per group
#define AT_VT (AT_KS + 2 * KS_G)           // 10880
#define VT_G  (2 * 64 * 36)                // 4608 per group
#define AT_PS (AT_VT + 2 * VT_G)           // 20096
#define PS_G  (32 * 36)                    // 1152 per group
#define AT_TOTAL (AT_PS + 2 * PS_G)        // 22400 words = 89600 bytes
#define KBUF_B (32 * 68 * 4)
#define VBUF_B (64 * 36 * 4)

__global__ __launch_bounds__(128) void attn_kernel(float* __restrict__ out)
{
    extern __shared__ uint32_t smu[];
    const int tid  = threadIdx.x;
    const int warp = tid >> 5;
    const int lane = tid & 31;
    const int gID  = lane >> 2;
    const int tig  = lane & 3;
    const int grp  = warp >> 1;
    const int wg   = warp & 1;
    const int lt   = tid & 63;
    const int q8   = lane & 7;
    const int sel  = lane >> 3;

    uint32_t (*Qs)[68] = (uint32_t (*)[68])(smu + AT_QS);
    uint32_t (*Ps)[36] = (uint32_t (*)[36])(smu + AT_PS + grp * PS_G);
    float* Co  = (float*)(smu + AT_PS);
    float* Cml = Co + 2048;

    const uint32_t qs_a = smem_u32(smu + AT_QS);
    const uint32_t ks_a = smem_u32(smu + AT_KS + grp * KS_G);
    const uint32_t vt_a = smem_u32(smu + AT_VT + grp * VT_G);
    const uint32_t ps_a = smem_u32(smu + AT_PS + grp * PS_G);

    const int b  = blockIdx.x & 7;
    const int qt = 63 - (blockIdx.x >> 3);     // heavy tiles first
    const int q0 = qt * 32;

    const uint32_t* Qg  = g_Q + ((size_t)b * TT + q0) * HH;
    const uint32_t* Kg  = g_K + (size_t)b * TT * HH;
    const uint32_t* Vtg = g_V + (size_t)b * HH * TT;

    // Stage Q (tf32, pre-scaled): plain copies, once
    #pragma unroll
    for (int it = 0; it < 4; it++) {
        const int s  = tid + it * 128;
        const int r  = s >> 4;
        const int c4 = (s & 15) * 4;
        *(uint4*)&Qs[r][c4] = *(const uint4*)(Qg + (size_t)r * HH + c4);
    }
    __syncthreads();

    // Per-lane ldmatrix base addresses
    const uint32_t a_q = qs_a + ((16 * wg + q8 + 8 * (sel & 1)) * 68 + (sel >> 1) * 4) * 4;
    const uint32_t a_p = ps_a + ((16 * wg + q8 + 8 * (sel & 1)) * 36 + (sel >> 1) * 4) * 4;
    const uint32_t b_k = ks_a + ((q8 + 8 * (sel >> 1)) * 68 + (sel & 1) * 4) * 4;
    const uint32_t b_v = vt_a + ((q8 + 8 * (sel >> 1)) * 36 + (sel & 1) * 4) * 4;

    float o[8][4] = {};
    float m0 = -1e30f, m1 = -1e30f, l0 = 0.f, l1 = 0.f;

    const int jfirst = grp * 32;
    if (jfirst <= q0) {
        // prefetch first tile into buffer 0
        #pragma unroll
        for (int it = 0; it < 8; it++) {
            const int s = lt + it * 64;
            { const int r = s >> 4, c4 = (s & 15) * 4;
              CP_ASYNC16(ks_a + (r * 68 + c4) * 4, Kg + (size_t)(jfirst + r) * HH + c4); }
            { const int r = s >> 3, c4 = (s & 7) * 4;
              CP_ASYNC16(vt_a + (r * 36 + c4) * 4, Vtg + (size_t)r * TT + jfirst + c4); }
        }
        CP_COMMIT;
    }

    int buf = 0;
    for (int j0 = jfirst; j0 <= q0; j0 += 64) {
        BARG(grp + 1);                       // all group threads past prior compute
        const bool last = (j0 + 64 > q0);
        if (!last) {
            const int jn = j0 + 64;
            const uint32_t kd = ks_a + (buf ^ 1) * KBUF_B;
            const uint32_t vd = vt_a + (buf ^ 1) * VBUF_B;
            #pragma unroll
            for (int it = 0; it < 8; it++) {
                const int s = lt + it * 64;
                { const int r = s >> 4, c4 = (s & 15) * 4;
                  CP_ASYNC16(kd + (r * 68 + c4) * 4, Kg + (size_t)(jn + r) * HH + c4); }
                { const int r = s >> 3, c4 = (s & 7) * 4;
                  CP_ASYNC16(vd + (r * 36 + c4) * 4, Vtg + (size_t)r * TT + jn + c4); }
            }
            CP_COMMIT;
        }
        if (last) { CP_WAIT0; } else { CP_WAIT1; }
        BARG(grp + 1);                       // current tile visible to whole group

        const uint32_t kb = b_k + buf * KBUF_B;
        const uint32_t vb = b_v + buf * VBUF_B;

        // ---- S = Q.K^T  (ldmatrix fragments) ----
        float s4[4][4] = {};
        #pragma unroll
        for (int ks = 0; ks < 8; ks++) {
            uint32_t a0, a1, a2, a3, k00, k01, k02, k03, k10, k11, k12, k13;
            ldsm4(a0, a1, a2, a3, a_q + ks * 32);
            ldsm4(k00, k01, k02, k03, kb + ks * 32);                  // j-tiles 0,8
            ldsm4(k10, k11, k12, k13, kb + 16 * 68 * 4 + ks * 32);    // j-tiles 16,24
            mma8(s4[0], a0, a1, a2, a3, k00, k01);
            mma8(s4[1], a0, a1, a2, a3, k02, k03);
            mma8(s4[2], a0, a1, a2, a3, k10, k11);
            mma8(s4[3], a0, a1, a2, a3, k12, k13);
        }

        // Causal mask: only the diagonal tile
        if (j0 == q0) {
            const int ql0 = 16 * wg + gID;
            const int ql1 = ql0 + 8;
            #pragma unroll
            for (int nt = 0; nt < 4; nt++) {
                const int jc = nt * 8 + 2 * tig;
                if (jc     > ql0) s4[nt][0] = -1e30f;
                if (jc + 1 > ql0) s4[nt][1] = -1e30f;
                if (jc     > ql1) s4[nt][2] = -1e30f;
                if (jc + 1 > ql1) s4[nt][3] = -1e30f;
            }
        }

        // ---- online softmax ----
        float mx0 = -1e30f, mx1 = -1e30f;
        #pragma unroll
        for (int nt = 0; nt < 4; nt++) {
            mx0 = fmaxf(mx0, fmaxf(s4[nt][0], s4[nt][1]));
            mx1 = fmaxf(mx1, fmaxf(s4[nt][2], s4[nt][3]));
        }
        mx0 = fmaxf(mx0, __shfl_xor_sync(0xffffffffu, mx0, 1));
        mx0 = fmaxf(mx0, __shfl_xor_sync(0xffffffffu, mx0, 2));
        mx1 = fmaxf(mx1, __shfl_xor_sync(0xffffffffu, mx1, 1));
        mx1 = fmaxf(mx1, __shfl_xor_sync(0xffffffffu, mx1, 2));

        const float mn0 = fmaxf(m0, mx0);
        const float mn1 = fmaxf(m1, mx1);
        const float al0 = ex2f(m0 - mn0);
        const float al1 = ex2f(m1 - mn1);
        m0 = mn0; m1 = mn1;

        float ps0 = 0.f, ps1 = 0.f;
        #pragma unroll
        for (int nt = 0; nt < 4; nt++) {
            s4[nt][0] = ex2f(s4[nt][0] - mn0);  ps0 += s4[nt][0];
            s4[nt][1] = ex2f(s4[nt][1] - mn0);  ps0 += s4[nt][1];
            s4[nt][2] = ex2f(s4[nt][2] - mn1);  ps1 += s4[nt][2];
            s4[nt][3] = ex2f(s4[nt][3] - mn1);  ps1 += s4[nt][3];
        }
        ps0 += __shfl_xor_sync(0xffffffffu, ps0, 1);
        ps0 += __shfl_xor_sync(0xffffffffu, ps0, 2);
        ps1 += __shfl_xor_sync(0xffffffffu, ps1, 1);
        ps1 += __shfl_xor_sync(0xffffffffu, ps1, 2);

        l0 = l0 * al0 + ps0;
        l1 = l1 * al1 + ps1;
        #pragma unroll
        for (int nt = 0; nt < 8; nt++) {
            o[nt][0] *= al0;  o[nt][1] *= al0;
            o[nt][2] *= al1;  o[nt][3] *= al1;
        }

        // ---- P -> warp-private smem, then O += P.V (ldmatrix fragments) ----
        {
            const int r0 = 16 * wg + gID;
            #pragma unroll
            for (int nt = 0; nt < 4; nt++) {
                const int col = nt * 8 + 2 * tig;
                *(uint2*)&Ps[r0][col]     = make_uint2(f2tf(s4[nt][0]), f2tf(s4[nt][1]));
                *(uint2*)&Ps[r0 + 8][col] = make_uint2(f2tf(s4[nt][2]), f2tf(s4[nt][3]));
            }
        }
        __syncwarp();

        #pragma unroll
        for (int ks = 0; ks < 4; ks++) {
            uint32_t a0, a1, a2, a3;
            uint32_t v00, v01, v02, v03, v10, v11, v12, v13;
            uint32_t v20, v21, v22, v23, v30, v31, v32, v33;
            ldsm4(a0, a1, a2, a3, a_p + ks * 32);
            ldsm4(v00, v01, v02, v03, vb + ks * 32);                  // d-tiles 0,8
            ldsm4(v10, v11, v12, v13, vb + 16 * 36 * 4 + ks * 32);    // d-tiles 16,24
            ldsm4(v20, v21, v22, v23, vb + 32 * 36 * 4 + ks * 32);    // d-tiles 32,40
            ldsm4(v30, v31, v32, v33, vb + 48 * 36 * 4 + ks * 32);    // d-tiles 48,56
            mma8(o[0], a0, a1, a2, a3, v00, v01);
            mma8(o[1], a0, a1, a2, a3, v02, v03);
            mma8(o[2], a0, a1, a2, a3, v10, v11);
            mma8(o[3], a0, a1, a2, a3, v12, v13);
            mma8(o[4], a0, a1, a2, a3, v20, v21);
            mma8(o[5], a0, a1, a2, a3, v22, v23);
            mma8(o[6], a0, a1, a2, a3, v30, v31);
            mma8(o[7], a0, a1, a2, a3, v32, v33);
        }

        buf ^= 1;
    }

    // ---- merge the two groups' partials (Co/Cml overlay dead Ps region) ----
    __syncthreads();   // both groups fully done with Ps before overlay write

    if (grp == 1) {
        #pragma unroll
        for (int nt = 0; nt < 8; nt++)
            #pragma unroll
            for (int c = 0; c < 4; c++)
                Co[((wg * 8 + nt) * 4 + c) * 32 + lane] = o[nt][c];
        Cml[(wg * 4 + 0) * 32 + lane] = m0;
        Cml[(wg * 4 + 1) * 32 + lane] = m1;
        Cml[(wg * 4 + 2) * 32 + lane] = l0;
        Cml[(wg * 4 + 3) * 32 + lane] = l1;
    }
    __syncthreads();

    if (grp == 0) {
        const float m0p = Cml[(wg * 4 + 0) * 32 + lane];
        const float m1p = Cml[(wg * 4 + 1) * 32 + lane];
        const float l0p = Cml[(wg * 4 + 2) * 32 + lane];
        const float l1p = Cml[(wg * 4 + 3) * 32 + lane];

        const float M0 = fmaxf(m0, m0p), M1 = fmaxf(m1, m1p);
        const float s00 = ex2f(m0 - M0), s01 = ex2f(m0p - M0);
        const float s10 = ex2f(m1 - M1), s11 = ex2f(m1p - M1);
        const float i0 = 1.f / (l0 * s00 + l0p * s01);
        const float i1 = 1.f / (l1 * s10 + l1p * s11);

        const int row = q0 + 16 * wg + gID;
        float* Ob = out + (size_t)b * TT * HH;
        #pragma unroll
        for (int nt = 0; nt < 8; nt++) {
            const int col = nt * 8 + 2 * tig;
            const float p0 = Co[((wg * 8 + nt) * 4 + 0) * 32 + lane];
            const float p1 = Co[((wg * 8 + nt) * 4 + 1) * 32 + lane];
            const float p2 = Co[((wg * 8 + nt) * 4 + 2) * 32 + lane];
            const float p3 = Co[((wg * 8 + nt) * 4 + 3) * 32 + lane];
            *(float2*)(Ob + (size_t)row * HH + col) =
                make_float2((o[nt][0] * s00 + p0 * s01) * i0,
                            (o[nt][1] * s00 + p1 * s01) * i0);
            *(float2*)(Ob + (size_t)(row + 8) * HH + col) =
                make_float2((o[nt][2] * s10 + p2 * s11) * i1,
                            (o[nt][3] * s10 + p3 * s11) * i1);
        }
    }
}

// ---------------------------------------------------------------------------
extern "C" void kernel_launch(void* const* d_in, const int* in_sizes, int n_in,
                              void* d_out, int out_size)
{
    const float* x  = (const float*)d_in[0];
    const float* Wk = (const float*)d_in[1];
    const float* Wq = (const float*)d_in[2];
    const float* Wv = (const float*)d_in[3];
    float* out = (float*)d_out;

    const int smem_bytes = AT_TOTAL * (int)sizeof(uint32_t);   // 89600
    cudaFuncSetAttribute(attn_kernel, cudaFuncAttributeMaxDynamicSharedMemorySize, smem_bytes);

    proj_kernel<<<MM / 64, 128>>>(x, Wk, Wq, Wv);

    attn_kernel<<<BB * (TT / 32), 128, smem_bytes>>>(out);
}